// round 8
// baseline (speedup 1.0000x reference)
#include <cuda_runtime.h>
#include <math.h>

#define NN    8192
#define NL    16
#define NE    (NN * 128)         /* 1048576 edges per layer */
#define EV    (NE / 4)           /* 262144 int4 edge-vectors */
#define NR    32                 /* global replicas for the REDG half */
#define NOUT  16
#define EOUT  (NN * NOUT)        /* 131072 output edges */

#define LGRID 296                /* 2 CTAs/SM (64 KB smem each) */
#define GS    (LGRID * 512)      /* 151552 threads; vec0: all, vec1: g+GS < EV */

// Per-CTA private slices (plain STG), replicated global accumulators (REDG half),
// reduced node values, logit accumulator. Scratch via __device__ (no allocs).
__device__ float g_cta[LGRID][NN];   /* 9.5 MB */
__device__ float g_acc[NR][NN];      /* 1 MB   */
__device__ float g_val[NN];
__device__ float g_oacc[NOUT];

__device__ __forceinline__ float lrelu(float v) { return v >= 0.f ? v : 0.01f * v; }

// Zero global replicas + logit accumulator (slices are fully overwritten each layer).
__global__ void init_kernel() {
    int i = blockIdx.x * blockDim.x + threadIdx.x;      // 256*256 = 65536 float4
    ((float4*)g_acc)[i] = make_float4(0.f, 0.f, 0.f, 0.f);
    if (i < NOUT) g_oacc[i] = 0.f;
}

// One hidden layer, hybrid scatter:
//   vec0 (58% of edges) -> smem atomics into the CTA-private accumulator
//   vec1 (42% of edges) -> global REDG into 32 replicated accumulators
// The two RMW streams drain on independent back-ends (smem banks vs LTS ALUs).
__global__ void __launch_bounds__(512, 2) layer_kernel(
    const int4*   __restrict__ src,
    const int4*   __restrict__ dst,
    const float4* __restrict__ w,
    const float*  __restrict__ vin)
{
    extern __shared__ float smem[];
    float* s_vals = smem;        // [0, 8192)    staged node values
    float* s_acc  = smem + NN;   // [8192,16384) CTA-private accumulator

    const int tid = threadIdx.x;
    const int bid = blockIdx.x;
    const int g   = bid * 512 + tid;          // vec0 index, always < GS <= EV
    const int g1  = g + GS;                    // vec1 index, if < EV

    // Prefetch vec0 edges (streaming) before the staging barrier.
    int4   es0 = __ldcs(&src[g]);
    int4   ed0 = __ldcs(&dst[g]);
    float4 ew0 = __ldcs(&w[g]);

    // Stage node values and zero the private accumulator.
    const float4* vin4 = (const float4*)vin;
    float4* s4 = (float4*)s_vals;
    float4* z4 = (float4*)s_acc;
    #pragma unroll
    for (int k = 0; k < 4; ++k) {
        int i = tid + k * 512;
        s4[i] = vin4[i];
        z4[i] = make_float4(0.f, 0.f, 0.f, 0.f);
    }
    __syncthreads();

    // vec0 -> smem atomics (per-CTA private, no cross-CTA contention)
    atomicAdd(&s_acc[ed0.x], s_vals[es0.x] * ew0.x);
    atomicAdd(&s_acc[ed0.y], s_vals[es0.y] * ew0.y);
    atomicAdd(&s_acc[ed0.z], s_vals[es0.z] * ew0.z);
    atomicAdd(&s_acc[ed0.w], s_vals[es0.w] * ew0.w);

    // vec1 -> global REDG into replica (warp, CTA-parity) of the 1 MB window
    if (g1 < EV) {
        int4   es1 = __ldcs(&src[g1]);
        int4   ed1 = __ldcs(&dst[g1]);
        float4 ew1 = __ldcs(&w[g1]);
        float* __restrict__ gout = &g_acc[(tid >> 5) + ((bid & 1) << 4)][0];
        atomicAdd(&gout[ed1.x], s_vals[es1.x] * ew1.x);
        atomicAdd(&gout[ed1.y], s_vals[es1.y] * ew1.y);
        atomicAdd(&gout[ed1.z], s_vals[es1.z] * ew1.z);
        atomicAdd(&gout[ed1.w], s_vals[es1.w] * ew1.w);
    }

    __syncthreads();

    // Flush the private accumulator to this CTA's global slice (plain stores).
    float4* slice4 = (float4*)g_cta[bid];
    const float4* a4 = (const float4*)s_acc;
    #pragma unroll
    for (int k = 0; k < 4; ++k) {
        int i = tid + k * 512;
        slice4[i] = a4[i];
    }
}

// Fold 296 slices + 32 replicas into g_val (activated), re-zero replicas.
// 8 CTAs x 256 threads, one float4 (4 nodes) per thread; ~10.5 MB L2-resident.
__global__ void __launch_bounds__(256) reduce_kernel() {
    const int i = blockIdx.x * blockDim.x + threadIdx.x;   // < 2048 float4
    float4 s = make_float4(0.f, 0.f, 0.f, 0.f);
    #pragma unroll 4
    for (int r = 0; r < NR; ++r) {
        float4 v = ((const float4*)g_acc[r])[i];
        ((float4*)g_acc[r])[i] = make_float4(0.f, 0.f, 0.f, 0.f);
        s.x += v.x; s.y += v.y; s.z += v.z; s.w += v.w;
    }
    #pragma unroll 8
    for (int c = 0; c < LGRID; ++c) {
        float4 v = ((const float4*)g_cta[c])[i];
        s.x += v.x; s.y += v.y; s.z += v.z; s.w += v.w;
    }
    ((float4*)g_val)[i] = make_float4(lrelu(s.x), lrelu(s.y), lrelu(s.z), lrelu(s.w));
}

// Output layer: 131072 edges into 16 logits. Per-CTA smem bins, one global
// atomic merge per bin per CTA. g_val is already activated.
__global__ void __launch_bounds__(256) out_kernel(
    const int*   __restrict__ osrc,
    const int*   __restrict__ odst,
    const float* __restrict__ ow)
{
    __shared__ float s_acc[NOUT];
    if (threadIdx.x < NOUT) s_acc[threadIdx.x] = 0.f;
    __syncthreads();

    const int g  = blockIdx.x * blockDim.x + threadIdx.x;
    const int gs = gridDim.x * blockDim.x;
    for (int i = g; i < EOUT; i += gs) {
        atomicAdd(&s_acc[odst[i]], g_val[osrc[i]] * ow[i]);
    }
    __syncthreads();
    if (threadIdx.x < NOUT) atomicAdd(&g_oacc[threadIdx.x], s_acc[threadIdx.x]);
}

// lrelu + softmax over the 16 logits; one warp.
__global__ void softmax_kernel(float* __restrict__ out) {
    const int t = threadIdx.x;                  // 32 threads
    float v = (t < NOUT) ? lrelu(g_oacc[t]) : -INFINITY;
    float m = v;
    #pragma unroll
    for (int o = 8; o > 0; o >>= 1) m = fmaxf(m, __shfl_xor_sync(0xffffffffu, m, o));
    float e = (t < NOUT) ? __expf(v - m) : 0.f;
    float s = e;
    #pragma unroll
    for (int o = 8; o > 0; o >>= 1) s += __shfl_xor_sync(0xffffffffu, s, o);
    if (t < NOUT) out[t] = e / s;
}

extern "C" void kernel_launch(void* const* d_in, const int* in_sizes, int n_in,
                              void* d_out, int out_size)
{
    // metadata order: x, edge_w, out_w, edge_src, edge_dst, out_src, out_dst
    const float* x        = (const float*)d_in[0];
    const float* edge_w   = (const float*)d_in[1];
    const float* out_w    = (const float*)d_in[2];
    const int*   edge_src = (const int*)  d_in[3];
    const int*   edge_dst = (const int*)  d_in[4];
    const int*   out_src  = (const int*)  d_in[5];
    const int*   out_dst  = (const int*)  d_in[6];
    float* out = (float*)d_out;

    float* val = nullptr;
    cudaGetSymbolAddress((void**)&val, g_val);   // capture-safe, not a stream op

    // 64 KB dynamic smem opt-in (idempotent, capture-safe).
    cudaFuncSetAttribute(layer_kernel,
                         cudaFuncAttributeMaxDynamicSharedMemorySize, 65536);

    init_kernel<<<256, 256>>>();

    for (int l = 0; l < NL; ++l) {
        const float* vin = (l == 0) ? x : val;
        const size_t off = (size_t)l * NE;
        layer_kernel<<<LGRID, 512, 65536>>>(
            (const int4*)(edge_src + off),
            (const int4*)(edge_dst + off),
            (const float4*)(edge_w + off),
            vin);
        reduce_kernel<<<8, 256>>>();
    }

    out_kernel<<<148, 256>>>(out_src, out_dst, out_w);
    softmax_kernel<<<1, 32>>>(out);
}

// round 10
// speedup vs baseline: 3.1109x; 3.1109x over previous
#include <cuda_runtime.h>
#include <math.h>

#define NN    8192
#define NL    16
#define NE    (NN * 128)         /* 1048576 edges per layer */
#define EV    (NE / 4)           /* 262144 int4 edge-vectors */
#define NR    16                 /* accumulator replicas (L2 decontention) */
#define NOUT  16
#define EOUT  (NN * NOUT)        /* 131072 output edges */

#define LGRID 128                /* 1 CTA/SM; 128*512 threads * 4 vecs = EV exactly */

// Replicated scatter accumulators (512 KB -> spreads over LTS partitions),
// reduced node values, output logit accumulator. Scratch via __device__ (no allocs).
__device__ float g_acc[NR][NN];
__device__ float g_val[NN];
__device__ float g_oacc[NOUT];

__device__ __forceinline__ float lrelu(float v) { return v >= 0.f ? v : 0.01f * v; }

// Zero all replicas + logit accumulator.
__global__ void init_kernel() {
    int i = blockIdx.x * blockDim.x + threadIdx.x;      // 128*256 = 32768 float4
    ((float4*)g_acc)[i] = make_float4(0.f, 0.f, 0.f, 0.f);
    if (i < NOUT) g_oacc[i] = 0.f;
}

// One hidden layer. 128 CTAs x 512 threads, ONE CTA per SM: no cross-CTA
// L1tex-queue contention. Each thread owns exactly 4 int4 edge-vectors
// (16 edges); all 12 edge LDG.128s are issued up front (high per-thread MLP)
// before the staging barrier. Scatter via REDG into 16 replicated accumulators
// (warp w -> replica w).
__global__ void __launch_bounds__(512, 1) layer_kernel(
    const int4*   __restrict__ src,
    const int4*   __restrict__ dst,
    const float4* __restrict__ w,
    const float*  __restrict__ vin)
{
    __shared__ float s_vals[NN];
    const int tid = threadIdx.x;
    const int g   = blockIdx.x * 512 + tid;       // < 65536

    // Front-batched streaming loads: 4 vecs, strided by 65536 vectors.
    int4 es0 = __ldcs(&src[g]);
    int4 es1 = __ldcs(&src[g + 65536]);
    int4 es2 = __ldcs(&src[g + 131072]);
    int4 es3 = __ldcs(&src[g + 196608]);
    int4 ed0 = __ldcs(&dst[g]);
    int4 ed1 = __ldcs(&dst[g + 65536]);
    int4 ed2 = __ldcs(&dst[g + 131072]);
    int4 ed3 = __ldcs(&dst[g + 196608]);
    float4 ew0 = __ldcs(&w[g]);
    float4 ew1 = __ldcs(&w[g + 65536]);
    float4 ew2 = __ldcs(&w[g + 131072]);
    float4 ew3 = __ldcs(&w[g + 196608]);

    // Stage node values (already activated by reduce_kernel / raw x for layer 0).
    const float4* vin4 = (const float4*)vin;
    float4* s4 = (float4*)s_vals;
    #pragma unroll
    for (int k = 0; k < 4; ++k) {
        int i = tid + k * 512;
        s4[i] = vin4[i];
    }
    __syncthreads();

    // Warp -> replica mapping (16 warps per CTA, NR = 16).
    float* __restrict__ out = &g_acc[tid >> 5][0];

    atomicAdd(&out[ed0.x], s_vals[es0.x] * ew0.x);
    atomicAdd(&out[ed0.y], s_vals[es0.y] * ew0.y);
    atomicAdd(&out[ed0.z], s_vals[es0.z] * ew0.z);
    atomicAdd(&out[ed0.w], s_vals[es0.w] * ew0.w);
    atomicAdd(&out[ed1.x], s_vals[es1.x] * ew1.x);
    atomicAdd(&out[ed1.y], s_vals[es1.y] * ew1.y);
    atomicAdd(&out[ed1.z], s_vals[es1.z] * ew1.z);
    atomicAdd(&out[ed1.w], s_vals[es1.w] * ew1.w);
    atomicAdd(&out[ed2.x], s_vals[es2.x] * ew2.x);
    atomicAdd(&out[ed2.y], s_vals[es2.y] * ew2.y);
    atomicAdd(&out[ed2.z], s_vals[es2.z] * ew2.z);
    atomicAdd(&out[ed2.w], s_vals[es2.w] * ew2.w);
    atomicAdd(&out[ed3.x], s_vals[es3.x] * ew3.x);
    atomicAdd(&out[ed3.y], s_vals[es3.y] * ew3.y);
    atomicAdd(&out[ed3.z], s_vals[es3.z] * ew3.z);
    atomicAdd(&out[ed3.w], s_vals[es3.w] * ew3.w);
}

// Fold the 16 replicas into g_val (with activation) and re-zero them for the
// next layer. 32 CTAs x 256 threads = 8192, one node per thread; coalesced,
// ~1 MB of L2-resident traffic.
__global__ void __launch_bounds__(256) reduce_kernel() {
    const int i = blockIdx.x * blockDim.x + threadIdx.x;
    float s = 0.f;
    #pragma unroll
    for (int r = 0; r < NR; ++r) {
        s += g_acc[r][i];
        g_acc[r][i] = 0.f;
    }
    g_val[i] = lrelu(s);
}

// Output layer: 131072 edges into 16 logits. Per-CTA smem bins, one global
// atomic merge per bin per CTA. g_val is already activated.
__global__ void __launch_bounds__(256) out_kernel(
    const int*   __restrict__ osrc,
    const int*   __restrict__ odst,
    const float* __restrict__ ow)
{
    __shared__ float s_acc[NOUT];
    if (threadIdx.x < NOUT) s_acc[threadIdx.x] = 0.f;
    __syncthreads();

    const int g  = blockIdx.x * blockDim.x + threadIdx.x;
    const int gs = gridDim.x * blockDim.x;
    for (int i = g; i < EOUT; i += gs) {
        atomicAdd(&s_acc[odst[i]], g_val[osrc[i]] * ow[i]);
    }
    __syncthreads();
    if (threadIdx.x < NOUT) atomicAdd(&g_oacc[threadIdx.x], s_acc[threadIdx.x]);
}

// lrelu + softmax over the 16 logits; one warp.
__global__ void softmax_kernel(float* __restrict__ out) {
    const int t = threadIdx.x;                  // 32 threads
    float v = (t < NOUT) ? lrelu(g_oacc[t]) : -INFINITY;
    float m = v;
    #pragma unroll
    for (int o = 8; o > 0; o >>= 1) m = fmaxf(m, __shfl_xor_sync(0xffffffffu, m, o));
    float e = (t < NOUT) ? __expf(v - m) : 0.f;
    float s = e;
    #pragma unroll
    for (int o = 8; o > 0; o >>= 1) s += __shfl_xor_sync(0xffffffffu, s, o);
    if (t < NOUT) out[t] = e / s;
}

extern "C" void kernel_launch(void* const* d_in, const int* in_sizes, int n_in,
                              void* d_out, int out_size)
{
    // metadata order: x, edge_w, out_w, edge_src, edge_dst, out_src, out_dst
    const float* x        = (const float*)d_in[0];
    const float* edge_w   = (const float*)d_in[1];
    const float* out_w    = (const float*)d_in[2];
    const int*   edge_src = (const int*)  d_in[3];
    const int*   edge_dst = (const int*)  d_in[4];
    const int*   out_src  = (const int*)  d_in[5];
    const int*   out_dst  = (const int*)  d_in[6];
    float* out = (float*)d_out;

    float* val = nullptr;
    cudaGetSymbolAddress((void**)&val, g_val);   // capture-safe, not a stream op

    init_kernel<<<128, 256>>>();

    for (int l = 0; l < NL; ++l) {
        const float* vin = (l == 0) ? x : val;
        const size_t off = (size_t)l * NE;
        layer_kernel<<<LGRID, 512>>>(
            (const int4*)(edge_src + off),
            (const int4*)(edge_dst + off),
            (const float4*)(edge_w + off),
            vin);
        reduce_kernel<<<32, 256>>>();
    }

    out_kernel<<<148, 256>>>(out_src, out_dst, out_w);
    softmax_kernel<<<1, 32>>>(out);
}